// round 8
// baseline (speedup 1.0000x reference)
#include <cuda_runtime.h>
#include <math.h>

#define BATCH   16
#define DMODEL  512
#define DSTATE  64
#define LEN     4096
#define TT      32

// ---------------- scratch (device globals: no allocations allowed) ----------
__device__ __align__(16) float g_zr[DMODEL*DSTATE];
__device__ __align__(16) float g_zi[DMODEL*DSTATE];
__device__ __align__(16) float g_wr[DMODEL*DSTATE];
__device__ __align__(16) float g_wi[DMODEL*DSTATE];
__device__ __align__(16) float g_w2r[DMODEL*DSTATE];
__device__ __align__(16) float g_w2i[DMODEL*DSTATE];
__device__ __align__(16) float g_gelu[(size_t)BATCH*DMODEL*LEN];   // 128 MB
__device__ __align__(16) float g_pooled[BATCH*DMODEL];
// W pre-packed into mma fragment order (tf32 bits): [rblk8][kt32][h2][mf8][lane32][reg4]
__device__ __align__(16) unsigned int g_Wp[8*32*2048];

__device__ __forceinline__ unsigned int f2tf32(float x) {
    unsigned int r;
    asm("cvt.rna.tf32.f32 %0, %1;" : "=r"(r) : "f"(x));
    return r;
}

// ---------------- kernel 1: SSM constants (fp64 for phase accuracy) ---------
__global__ void k_params(const float* __restrict__ log_dt,
                         const float* __restrict__ log_A_real,
                         const float* __restrict__ A_imag,
                         const float* __restrict__ B_re,
                         const float* __restrict__ B_im,
                         const float* __restrict__ C_re,
                         const float* __restrict__ C_im) {
    int i = blockIdx.x * blockDim.x + threadIdx.x;
    if (i >= DMODEL * DSTATE) return;
    int d = i / DSTATE;
    double dt   = exp((double)log_dt[d]);
    double Ar   = -exp((double)log_A_real[i]);
    double Ai   = (double)A_imag[i];
    double dtAr = Ar * dt, dtAi = Ai * dt;
    double er = exp(dtAr);
    double zr = er * cos(dtAi), zi = er * sin(dtAi);
    double den  = Ar * Ar + Ai * Ai;
    double numr = zr - 1.0, numi = zi;
    double qr = (numr * Ar + numi * Ai) / den;
    double qi = (numi * Ar - numr * Ai) / den;
    double Br = (double)B_re[i], Bi = (double)B_im[i];
    double bbr = qr * Br - qi * Bi, bbi = qr * Bi + qi * Br;
    double Cr = (double)C_re[i], Ci = (double)C_im[i];
    double wr = Cr * bbr - Ci * bbi, wi = Cr * bbi + Ci * bbr;
    double eL = exp((double)LEN * dtAr);
    double ph = (double)LEN * dtAi;
    double zLr = eL * cos(ph), zLi = eL * sin(ph);
    double w2r = -(wr * zLr - wi * zLi);
    double w2i = -(wr * zLi + wi * zLr);
    g_zr[i] = (float)zr;  g_zi[i] = (float)zi;
    g_wr[i] = (float)wr;  g_wi[i] = (float)wi;
    g_w2r[i] = (float)w2r; g_w2i[i] = (float)w2i;
}

// ---------------- kernel 1b: pack W into tf32 mma fragment order ------------
// element (rblk, kt, h, mf8, lane, reg):
//   m = mf8*16 + (lane>>2) + 8*(reg&1)   (block row 0..127)
//   k = kt*16 + h*8 + (lane&3) + 4*(reg>>1)
//   wrow = (m<64) ? rblk*64+m : 448+rblk*64+m
__global__ void k_packW(const float* __restrict__ W) {
    int flat = blockIdx.x * blockDim.x + threadIdx.x;   // 524288 total
    int reg  = flat & 3;
    int lane = (flat >> 2) & 31;
    int mf8  = (flat >> 7) & 7;
    int h    = (flat >> 10) & 1;
    int kt   = (flat >> 11) & 31;
    int rb   = flat >> 16;
    int m = mf8 * 16 + (lane >> 2) + 8 * (reg & 1);
    int k = kt * 16 + h * 8 + (lane & 3) + 4 * (reg >> 1);
    int wrow = (m < 64) ? rb * 64 + m : 448 + rb * 64 + m;
    g_Wp[flat] = f2tf32(W[wrow * 512 + k]);
}

// ---------------- kernel 2: zero pooled accumulator -------------------------
__global__ void k_zero() {
    int i = blockIdx.x * blockDim.x + threadIdx.x;
    if (i < BATCH * DMODEL) g_pooled[i] = 0.0f;
}

// ---------------- kernel 3: two-pass backward scan (E-form) + skip + GELU ---
// y[x] = Re(E(x)),  E(L-1) = w*H0,  E(x-1) = z*E(x) + w2*u[x]
__global__ __launch_bounds__(64) void k_scan(const float* __restrict__ u,
                                             const float* __restrict__ Dp) {
    __shared__ float su[TT];
    __shared__ float sbuf[DSTATE][TT + 1];
    __shared__ float pbuf[2][TT];

    int bd = blockIdx.x;                 // b*DMODEL + d
    int d  = bd & (DMODEL - 1);
    const float* ub = u + (size_t)bd * LEN;
    float* gb = g_gelu + (size_t)bd * LEN;

    int n  = threadIdx.x;
    int dn = d * DSTATE + n;
    float zr = g_zr[dn],  zi = g_zi[dn];
    float wr = g_wr[dn],  wi = g_wi[dn];
    float w2r = g_w2r[dn], w2i = g_w2i[dn];
    float Dd = Dp[d];

    // ---- pass A: H0 = sum_j u[j] z^j  (Horner from the top, stable) ----
    float Hr = 0.0f, Hi = 0.0f;
    for (int x0 = LEN - TT; x0 >= 0; x0 -= TT) {
        __syncthreads();
        if (threadIdx.x < TT) su[threadIdx.x] = ub[x0 + threadIdx.x];
        __syncthreads();
        #pragma unroll
        for (int t = TT - 1; t >= 0; --t) {
            float uu = su[t];
            float hr = fmaf(zr, Hr, fmaf(-zi, Hi, uu));
            float hi = fmaf(zi, Hr, zr * Hi);
            Hr = hr; Hi = hi;
        }
    }
    float Er = fmaf(wr, Hr, -wi * Hi);   // E(L-1) = w * H0
    float Ei = fmaf(wr, Hi,  wi * Hr);

    // ---- pass B: emit y backward via single E recurrence ----
    int tred = threadIdx.x & 31;
    int nh   = threadIdx.x >> 5;
    for (int x0 = LEN - TT; x0 >= 0; x0 -= TT) {
        __syncthreads();
        if (threadIdx.x < TT) su[threadIdx.x] = ub[x0 + threadIdx.x];
        __syncthreads();
        #pragma unroll
        for (int t = TT - 1; t >= 0; --t) {
            sbuf[n][t] = Er;                          // y contribution at x=x0+t
            float uu = su[t];
            float er = fmaf(zr, Er, fmaf(-zi, Ei, w2r * uu));
            float ei = fmaf(zi, Er, fmaf( zr, Ei, w2i * uu));
            Er = er; Ei = ei;
        }
        __syncthreads();
        float acc = 0.0f;
        #pragma unroll
        for (int k = 0; k < 32; ++k) acc += sbuf[nh * 32 + k][tred];
        pbuf[nh][tred] = acc;
        __syncthreads();
        if (threadIdx.x < TT) {
            int t = threadIdx.x;
            float yv = pbuf[0][t] + pbuf[1][t] + Dd * su[t];
            float gv = 0.5f * yv * (1.0f + erff(yv * 0.7071067811865475f));
            gb[x0 + t] = gv;
        }
    }
}

// ---------------- kernel 4: tf32 tensor-core GEMM + GLU + mean fused --------
// C[1024,65536] = W[1024,512] @ YG[512,65536], block tile 128x128,
// 8 warps (wm 0..1 over M, wn 0..3 over N), warp tile 64x32, mma m16n8k8 tf32.
#define SA_STRIDE 2048                 // floats per A buffer (2 k8 x 8 mf x 128)
#define SB_GRP    66                   // per-(h,nf) group stride (64 + pad 2)
#define SB_STRIDE (32*SB_GRP)          // 2112 floats per B buffer

__device__ __forceinline__ void mma_tf32(float* c, const uint4 a, const uint2 b) {
    asm volatile(
        "mma.sync.aligned.m16n8k8.row.col.f32.tf32.tf32.f32 "
        "{%0,%1,%2,%3}, {%4,%5,%6,%7}, {%8,%9}, {%0,%1,%2,%3};"
        : "+f"(c[0]), "+f"(c[1]), "+f"(c[2]), "+f"(c[3])
        : "r"(a.x), "r"(a.y), "r"(a.z), "r"(a.w), "r"(b.x), "r"(b.y));
}

__global__ __launch_bounds__(256) void k_gemm(const float* __restrict__ bout) {
    __shared__ __align__(16) float sh[8576];
    float* sA = sh;                       // 2 x 2048
    float* sB = sh + 2 * SA_STRIDE;       // 2 x 2112

    int tid = threadIdx.x;
    int w = tid >> 5, lane = tid & 31;
    int wm = w & 1, wn = w >> 1;
    int rblk = blockIdx.x;                // 0..7
    int nblk = blockIdx.y;                // 0..511
    int col0 = nblk * 128;
    int b = col0 >> 12;
    const float* yg = g_gelu + (size_t)b * DMODEL * LEN + (col0 & (LEN - 1));
    const unsigned int* Wp = g_Wp + rblk * (32 * 2048);

    float acc[4][4][4];
    #pragma unroll
    for (int i = 0; i < 4; ++i)
        #pragma unroll
        for (int j = 0; j < 4; ++j)
            #pragma unroll
            for (int r = 0; r < 4; ++r) acc[i][j][r] = 0.0f;

    // ---- prologue: pack ktile 0 into buffer 0 ----
    #pragma unroll
    for (int i = 0; i < 2; ++i) {
        int ia = tid + i * 256;
        uint4 va = *reinterpret_cast<const uint4*>(Wp + (size_t)ia * 4);
        *reinterpret_cast<uint4*>(reinterpret_cast<unsigned int*>(sA) + ia * 4) = va;
        int k = ia >> 5, n0 = (ia & 31) << 2;
        float4 vb = *reinterpret_cast<const float4*>(yg + (size_t)k * LEN + n0);
        float v[4] = {vb.x, vb.y, vb.z, vb.w};
        int h = k >> 3, kk = k & 3, reg = (k >> 2) & 1;
        #pragma unroll
        for (int e = 0; e < 4; ++e) {
            int nn = n0 + e;
            int l = ((nn & 7) << 2) | kk;
            sB[(h * 16 + (nn >> 3)) * SB_GRP + l * 2 + reg] = __uint_as_float(f2tf32(v[e]));
        }
    }
    __syncthreads();

    for (int kt = 0; kt < 32; ++kt) {
        int buf = kt & 1;
        bool has = kt < 31;
        uint4 pa[2]; float4 pb[2];
        if (has) {
            #pragma unroll
            for (int i = 0; i < 2; ++i) {
                int ia = tid + i * 256;
                pa[i] = *reinterpret_cast<const uint4*>(Wp + (size_t)(kt + 1) * 2048 + (size_t)ia * 4);
                int k = ia >> 5, n0 = (ia & 31) << 2;
                pb[i] = *reinterpret_cast<const float4*>(yg + (size_t)((kt + 1) * 16 + k) * LEN + n0);
            }
        }
        // ---- compute on buf ----
        const float* sAb = sA + buf * SA_STRIDE;
        const float* sBb = sB + buf * SB_STRIDE;
        #pragma unroll
        for (int h = 0; h < 2; ++h) {
            uint4 af[4]; uint2 bf[4];
            #pragma unroll
            for (int mf = 0; mf < 4; ++mf)
                af[mf] = *reinterpret_cast<const uint4*>(sAb + ((h * 8 + wm * 4 + mf) * 128 + lane * 4));
            #pragma unroll
            for (int nf = 0; nf < 4; ++nf)
                bf[nf] = *reinterpret_cast<const uint2*>(sBb + (h * 16 + wn * 4 + nf) * SB_GRP + lane * 2);
            #pragma unroll
            for (int mf = 0; mf < 4; ++mf)
                #pragma unroll
                for (int nf = 0; nf < 4; ++nf)
                    mma_tf32(acc[mf][nf], af[mf], bf[nf]);
        }
        // ---- store prefetched tile to buf^1 ----
        if (has) {
            int nb = buf ^ 1;
            #pragma unroll
            for (int i = 0; i < 2; ++i) {
                int ia = tid + i * 256;
                *reinterpret_cast<uint4*>(reinterpret_cast<unsigned int*>(sA + nb * SA_STRIDE) + ia * 4) = pa[i];
                int k = ia >> 5, n0 = (ia & 31) << 2;
                float v[4] = {pb[i].x, pb[i].y, pb[i].z, pb[i].w};
                int h = k >> 3, kk = k & 3, reg = (k >> 2) & 1;
                float* sBn = sB + nb * SB_STRIDE;
                #pragma unroll
                for (int e = 0; e < 4; ++e) {
                    int nn = n0 + e;
                    int l = ((nn & 7) << 2) | kk;
                    sBn[(h * 16 + (nn >> 3)) * SB_GRP + l * 2 + reg] = __uint_as_float(f2tf32(v[e]));
                }
            }
        }
        __syncthreads();
    }

    // ---- epilogue: GLU + per-block column reduction ----
    float* Sg  = sh;                      // [64][129]
    float* red = sh + 64 * 129;           // [64][4]

    if (wm == 1) {                        // g rows (block rows 64..127)
        #pragma unroll
        for (int mf = 0; mf < 4; ++mf)
            #pragma unroll
            for (int hi = 0; hi < 2; ++hi) {
                int row = mf * 16 + (lane >> 2) + 8 * hi;       // g channel (0..63)
                float bo = bout[512 + rblk * 64 + row];
                #pragma unroll
                for (int nf = 0; nf < 4; ++nf)
                    #pragma unroll
                    for (int c01 = 0; c01 < 2; ++c01) {
                        int col = wn * 32 + nf * 8 + ((lane & 3) << 1) + c01;
                        float gv = acc[mf][nf][2 * hi + c01] + bo;
                        Sg[row * 129 + col] = 1.0f / (1.0f + expf(-gv));
                    }
            }
    }
    __syncthreads();
    if (wm == 0) {                        // a rows
        #pragma unroll
        for (int mf = 0; mf < 4; ++mf)
            #pragma unroll
            for (int hi = 0; hi < 2; ++hi) {
                int row = mf * 16 + (lane >> 2) + 8 * hi;
                float bo = bout[rblk * 64 + row];
                float rs = 0.0f;
                #pragma unroll
                for (int nf = 0; nf < 4; ++nf)
                    #pragma unroll
                    for (int c01 = 0; c01 < 2; ++c01) {
                        int col = wn * 32 + nf * 8 + ((lane & 3) << 1) + c01;
                        rs += (acc[mf][nf][2 * hi + c01] + bo) * Sg[row * 129 + col];
                    }
                rs += __shfl_xor_sync(0xffffffffu, rs, 1);
                rs += __shfl_xor_sync(0xffffffffu, rs, 2);
                if ((lane & 3) == 0) red[row * 4 + wn] = rs;
            }
    }
    __syncthreads();
    if (tid < 64) {
        float s = red[tid * 4] + red[tid * 4 + 1] + red[tid * 4 + 2] + red[tid * 4 + 3];
        atomicAdd(&g_pooled[b * DMODEL + rblk * 64 + tid], s);
    }
}

// ---------------- kernel 5: mean scale + decoder ----------------------------
__global__ void k_final(const float* __restrict__ Wd,
                        const float* __restrict__ bd,
                        float* __restrict__ out) {
    int b = blockIdx.x;
    __shared__ float r[256];
    float s = 0.0f;
    for (int c = threadIdx.x; c < DMODEL; c += 256)
        s += Wd[c] * g_pooled[b * DMODEL + c];
    r[threadIdx.x] = s;
    __syncthreads();
    for (int st = 128; st > 0; st >>= 1) {
        if (threadIdx.x < st) r[threadIdx.x] += r[threadIdx.x + st];
        __syncthreads();
    }
    if (threadIdx.x == 0) out[b] = r[0] * (1.0f / (float)LEN) + bd[0];
}

// ---------------- launch -----------------------------------------------------
extern "C" void kernel_launch(void* const* d_in, const int* in_sizes, int n_in,
                              void* d_out, int out_size) {
    const float* u          = (const float*)d_in[0];
    const float* log_dt     = (const float*)d_in[1];
    const float* log_A_real = (const float*)d_in[2];
    const float* A_imag     = (const float*)d_in[3];
    const float* B_re       = (const float*)d_in[4];
    const float* B_im       = (const float*)d_in[5];
    const float* C_re       = (const float*)d_in[6];
    const float* C_im       = (const float*)d_in[7];
    const float* Dp         = (const float*)d_in[8];
    const float* W_out      = (const float*)d_in[9];
    const float* b_out      = (const float*)d_in[10];
    const float* W_dec      = (const float*)d_in[11];
    const float* b_dec      = (const float*)d_in[12];
    float* out = (float*)d_out;

    k_params<<<(DMODEL * DSTATE + 127) / 128, 128>>>(log_dt, log_A_real, A_imag,
                                                     B_re, B_im, C_re, C_im);
    k_packW<<<(8 * 32 * 2048) / 256, 256>>>(W_out);
    k_zero<<<(BATCH * DMODEL + 255) / 256, 256>>>();
    k_scan<<<BATCH * DMODEL, 64>>>(u, Dp);
    dim3 gg(8, (BATCH * LEN) / 128);
    k_gemm<<<gg, 256>>>(b_out);
    k_final<<<BATCH, 256>>>(W_dec, b_dec, out);
}

// round 9
// speedup vs baseline: 1.3508x; 1.3508x over previous
#include <cuda_runtime.h>
#include <math.h>

#define BATCH   16
#define DMODEL  512
#define DSTATE  64
#define LEN     4096

// ---------------- scratch (device globals: no allocations allowed) ----------
__device__ __align__(16) float g_zr[DMODEL*DSTATE];
__device__ __align__(16) float g_zi[DMODEL*DSTATE];
__device__ __align__(16) float g_wr[DMODEL*DSTATE];
__device__ __align__(16) float g_wi[DMODEL*DSTATE];
__device__ __align__(16) float g_w2r[DMODEL*DSTATE];
__device__ __align__(16) float g_w2i[DMODEL*DSTATE];
__device__ __align__(16) float g_gelu[(size_t)BATCH*DMODEL*LEN];   // 128 MB
__device__ __align__(16) float g_pooled[BATCH*DMODEL];
// W pre-packed into mma fragment order (tf32 bits): [rblk8][kt32][h2][mf8][lane32][reg4]
__device__ __align__(16) unsigned int g_Wp[8*32*2048];

__device__ __forceinline__ unsigned int f2tf32(float x) {
    unsigned int r;
    asm("cvt.rna.tf32.f32 %0, %1;" : "=r"(r) : "f"(x));
    return r;
}

// ---------------- kernel 1: SSM constants (fp64 for phase accuracy) ---------
__global__ void k_params(const float* __restrict__ log_dt,
                         const float* __restrict__ log_A_real,
                         const float* __restrict__ A_imag,
                         const float* __restrict__ B_re,
                         const float* __restrict__ B_im,
                         const float* __restrict__ C_re,
                         const float* __restrict__ C_im) {
    int i = blockIdx.x * blockDim.x + threadIdx.x;
    if (i >= DMODEL * DSTATE) return;
    int d = i / DSTATE;
    double dt   = exp((double)log_dt[d]);
    double Ar   = -exp((double)log_A_real[i]);
    double Ai   = (double)A_imag[i];
    double dtAr = Ar * dt, dtAi = Ai * dt;
    double er = exp(dtAr);
    double zr = er * cos(dtAi), zi = er * sin(dtAi);
    double den  = Ar * Ar + Ai * Ai;
    double numr = zr - 1.0, numi = zi;
    double qr = (numr * Ar + numi * Ai) / den;
    double qi = (numi * Ar - numr * Ai) / den;
    double Br = (double)B_re[i], Bi = (double)B_im[i];
    double bbr = qr * Br - qi * Bi, bbi = qr * Bi + qi * Br;
    double Cr = (double)C_re[i], Ci = (double)C_im[i];
    double wr = Cr * bbr - Ci * bbi, wi = Cr * bbi + Ci * bbr;
    double eL = exp((double)LEN * dtAr);
    double ph = (double)LEN * dtAi;
    double zLr = eL * cos(ph), zLi = eL * sin(ph);
    double w2r = -(wr * zLr - wi * zLi);
    double w2i = -(wr * zLi + wi * zLr);
    g_zr[i] = (float)zr;  g_zi[i] = (float)zi;
    g_wr[i] = (float)wr;  g_wi[i] = (float)wi;
    g_w2r[i] = (float)w2r; g_w2i[i] = (float)w2i;
}

// ---------------- kernel 1b: pack W into tf32 mma fragment order ------------
__global__ void k_packW(const float* __restrict__ W) {
    int flat = blockIdx.x * blockDim.x + threadIdx.x;   // 524288 total
    int reg  = flat & 3;
    int lane = (flat >> 2) & 31;
    int mf8  = (flat >> 7) & 7;
    int h    = (flat >> 10) & 1;
    int kt   = (flat >> 11) & 31;
    int rb   = flat >> 16;
    int m = mf8 * 16 + (lane >> 2) + 8 * (reg & 1);
    int k = kt * 16 + h * 8 + (lane & 3) + 4 * (reg >> 1);
    int wrow = (m < 64) ? rb * 64 + m : 448 + rb * 64 + m;
    g_Wp[flat] = f2tf32(W[wrow * 512 + k]);
}

// ---------------- kernel 2: zero pooled accumulator -------------------------
__global__ void k_zero() {
    int i = blockIdx.x * blockDim.x + threadIdx.x;
    if (i < BATCH * DMODEL) g_pooled[i] = 0.0f;
}

// ---------------- kernel 3: Goertzel scan + skip + GELU ---------------------
// One warp per (b,d); 2 states per lane (n=lane, n=lane+32).
// Pass A: s(x) = u[x] + p s(x+1) + q s(x+2); H0 = s(0) - conj(z) s(1).
// Pass B: R(x) = p R(x+1) + q R(x+2) + c1 u[x+1] + c0 u[x+2],
//         c1 = w2r, c0 = -Re(conj(z) w2), primed from E(L-1) = w*H0.
__global__ __launch_bounds__(128) void k_scan(const float* __restrict__ u,
                                              const float* __restrict__ Dp) {
    __shared__ float sbuf[4][32][33];

    int wid  = threadIdx.x >> 5;
    int lane = threadIdx.x & 31;
    int bd = blockIdx.x * 4 + wid;
    int d  = bd & (DMODEL - 1);
    const float* ub = u + (size_t)bd * LEN;
    float* gb = g_gelu + (size_t)bd * LEN;
    float (*sb)[33] = sbuf[wid];

    int dn0 = d * DSTATE + lane;
    int dn1 = dn0 + 32;
    float zra = g_zr[dn0], zia = g_zi[dn0];
    float zrb = g_zr[dn1], zib = g_zi[dn1];
    float pa = 2.0f * zra, qa = -fmaf(zra, zra, zia * zia);
    float pb = 2.0f * zrb, qb = -fmaf(zrb, zrb, zib * zib);
    float Dd = Dp[d];

    // ---- pass A: Goertzel for both states (2 fma/state/step) ----
    float s1a = 0.f, s2a = 0.f, s1b = 0.f, s2b = 0.f;
    for (int x0 = LEN - 32; x0 >= 0; x0 -= 32) {
        float ul = ub[x0 + lane];
        #pragma unroll
        for (int t = 31; t >= 0; --t) {
            float uu = __shfl_sync(0xffffffffu, ul, t);
            float na = fmaf(pa, s1a, fmaf(qa, s2a, uu));
            float nb = fmaf(pb, s1b, fmaf(qb, s2b, uu));
            s2a = s1a; s1a = na;
            s2b = s1b; s1b = nb;
        }
    }
    // s1 = s(0), s2 = s(1)

    // ---- boundary priming (complex, once) ----
    float uL1 = __ldg(ub + LEN - 1);
    float c1a, c0a, r1a, r2a, c1b, c0b, r1b, r2b;
    {
        float wr = g_wr[dn0], wi = g_wi[dn0];
        float w2r = g_w2r[dn0], w2i = g_w2i[dn0];
        float H0r = fmaf(-zra, s2a, s1a), H0i = zia * s2a;
        float mr = fmaf(wr, H0r, -wi * H0i);
        float mi = fmaf(wr, H0i,  wi * H0r);
        float RL1 = mr;
        float RL2 = fmaf(zra, mr, fmaf(-zia, mi, w2r * uL1));
        c1a = w2r;
        c0a = -fmaf(zra, w2r, zia * w2i);
        float invq = 1.0f / qa;
        r1a = (RL2 - pa * RL1 - c1a * uL1) * invq;   // ghost R(L)
        r2a = (RL1 - pa * r1a) * invq;               // ghost R(L+1)
    }
    {
        float wr = g_wr[dn1], wi = g_wi[dn1];
        float w2r = g_w2r[dn1], w2i = g_w2i[dn1];
        float H0r = fmaf(-zrb, s2b, s1b), H0i = zib * s2b;
        float mr = fmaf(wr, H0r, -wi * H0i);
        float mi = fmaf(wr, H0i,  wi * H0r);
        float RL1 = mr;
        float RL2 = fmaf(zrb, mr, fmaf(-zib, mi, w2r * uL1));
        c1b = w2r;
        c0b = -fmaf(zrb, w2r, zib * w2i);
        float invq = 1.0f / qb;
        r1b = (RL2 - pb * RL1 - c1b * uL1) * invq;
        r2b = (RL1 - pb * r1b) * invq;
    }

    // ---- pass B: real 2nd-order emission (4 fma/state/step) ----
    float u1 = 0.f, u2 = 0.f;                        // ghost u[L], u[L+1]
    for (int x0 = LEN - 32; x0 >= 0; x0 -= 32) {
        float ul = ub[x0 + lane];
        #pragma unroll
        for (int t = 31; t >= 0; --t) {
            float uu = __shfl_sync(0xffffffffu, ul, t);
            float ta = fmaf(c1a, u1, c0a * u2);
            ta = fmaf(qa, r2a, ta);
            float Ra = fmaf(pa, r1a, ta);
            float tb = fmaf(c1b, u1, c0b * u2);
            tb = fmaf(qb, r2b, tb);
            float Rb = fmaf(pb, r1b, tb);
            sb[lane][t] = Ra + Rb;
            r2a = r1a; r1a = Ra;
            r2b = r1b; r1b = Rb;
            u2 = u1; u1 = uu;
        }
        __syncwarp();
        float acc = 0.f;
        #pragma unroll
        for (int k = 0; k < 32; ++k) acc += sb[k][lane];
        float yv = fmaf(Dd, ul, acc);
        float gv = 0.5f * yv * (1.0f + erff(yv * 0.7071067811865475f));
        gb[x0 + lane] = gv;
        __syncwarp();
    }
}

// ---------------- kernel 4: tf32 tensor-core GEMM + GLU + mean fused --------
#define SA_STRIDE 2048
#define SB_GRP    66
#define SB_STRIDE (32*SB_GRP)

__device__ __forceinline__ void mma_tf32(float* c, const uint4 a, const uint2 b) {
    asm volatile(
        "mma.sync.aligned.m16n8k8.row.col.f32.tf32.tf32.f32 "
        "{%0,%1,%2,%3}, {%4,%5,%6,%7}, {%8,%9}, {%0,%1,%2,%3};"
        : "+f"(c[0]), "+f"(c[1]), "+f"(c[2]), "+f"(c[3])
        : "r"(a.x), "r"(a.y), "r"(a.z), "r"(a.w), "r"(b.x), "r"(b.y));
}

__global__ __launch_bounds__(256) void k_gemm(const float* __restrict__ bout) {
    __shared__ __align__(16) float sh[8576];
    float* sA = sh;
    float* sB = sh + 2 * SA_STRIDE;

    int tid = threadIdx.x;
    int w = tid >> 5, lane = tid & 31;
    int wm = w & 1, wn = w >> 1;
    int rblk = blockIdx.x;
    int nblk = blockIdx.y;
    int col0 = nblk * 128;
    int b = col0 >> 12;
    const float* yg = g_gelu + (size_t)b * DMODEL * LEN + (col0 & (LEN - 1));
    const unsigned int* Wp = g_Wp + rblk * (32 * 2048);

    float acc[4][4][4];
    #pragma unroll
    for (int i = 0; i < 4; ++i)
        #pragma unroll
        for (int j = 0; j < 4; ++j)
            #pragma unroll
            for (int r = 0; r < 4; ++r) acc[i][j][r] = 0.0f;

    #pragma unroll
    for (int i = 0; i < 2; ++i) {
        int ia = tid + i * 256;
        uint4 va = *reinterpret_cast<const uint4*>(Wp + (size_t)ia * 4);
        *reinterpret_cast<uint4*>(reinterpret_cast<unsigned int*>(sA) + ia * 4) = va;
        int k = ia >> 5, n0 = (ia & 31) << 2;
        float4 vb = *reinterpret_cast<const float4*>(yg + (size_t)k * LEN + n0);
        float v[4] = {vb.x, vb.y, vb.z, vb.w};
        int h = k >> 3, kk = k & 3, reg = (k >> 2) & 1;
        #pragma unroll
        for (int e = 0; e < 4; ++e) {
            int nn = n0 + e;
            int l = ((nn & 7) << 2) | kk;
            sB[(h * 16 + (nn >> 3)) * SB_GRP + l * 2 + reg] = __uint_as_float(f2tf32(v[e]));
        }
    }
    __syncthreads();

    for (int kt = 0; kt < 32; ++kt) {
        int buf = kt & 1;
        bool has = kt < 31;
        uint4 pa[2]; float4 pb[2];
        if (has) {
            #pragma unroll
            for (int i = 0; i < 2; ++i) {
                int ia = tid + i * 256;
                pa[i] = *reinterpret_cast<const uint4*>(Wp + (size_t)(kt + 1) * 2048 + (size_t)ia * 4);
                int k = ia >> 5, n0 = (ia & 31) << 2;
                pb[i] = *reinterpret_cast<const float4*>(yg + (size_t)((kt + 1) * 16 + k) * LEN + n0);
            }
        }
        const float* sAb = sA + buf * SA_STRIDE;
        const float* sBb = sB + buf * SB_STRIDE;
        #pragma unroll
        for (int h = 0; h < 2; ++h) {
            uint4 af[4]; uint2 bf[4];
            #pragma unroll
            for (int mf = 0; mf < 4; ++mf)
                af[mf] = *reinterpret_cast<const uint4*>(sAb + ((h * 8 + wm * 4 + mf) * 128 + lane * 4));
            #pragma unroll
            for (int nf = 0; nf < 4; ++nf)
                bf[nf] = *reinterpret_cast<const uint2*>(sBb + (h * 16 + wn * 4 + nf) * SB_GRP + lane * 2);
            #pragma unroll
            for (int mf = 0; mf < 4; ++mf)
                #pragma unroll
                for (int nf = 0; nf < 4; ++nf)
                    mma_tf32(acc[mf][nf], af[mf], bf[nf]);
        }
        if (has) {
            int nb = buf ^ 1;
            #pragma unroll
            for (int i = 0; i < 2; ++i) {
                int ia = tid + i * 256;
                *reinterpret_cast<uint4*>(reinterpret_cast<unsigned int*>(sA + nb * SA_STRIDE) + ia * 4) = pa[i];
                int k = ia >> 5, n0 = (ia & 31) << 2;
                float v[4] = {pb[i].x, pb[i].y, pb[i].z, pb[i].w};
                int h = k >> 3, kk = k & 3, reg = (k >> 2) & 1;
                float* sBn = sB + nb * SB_STRIDE;
                #pragma unroll
                for (int e = 0; e < 4; ++e) {
                    int nn = n0 + e;
                    int l = ((nn & 7) << 2) | kk;
                    sBn[(h * 16 + (nn >> 3)) * SB_GRP + l * 2 + reg] = __uint_as_float(f2tf32(v[e]));
                }
            }
        }
        __syncthreads();
    }

    float* Sg  = sh;
    float* red = sh + 64 * 129;

    if (wm == 1) {
        #pragma unroll
        for (int mf = 0; mf < 4; ++mf)
            #pragma unroll
            for (int hi = 0; hi < 2; ++hi) {
                int row = mf * 16 + (lane >> 2) + 8 * hi;
                float bo = bout[512 + rblk * 64 + row];
                #pragma unroll
                for (int nf = 0; nf < 4; ++nf)
                    #pragma unroll
                    for (int c01 = 0; c01 < 2; ++c01) {
                        int col = wn * 32 + nf * 8 + ((lane & 3) << 1) + c01;
                        float gv = acc[mf][nf][2 * hi + c01] + bo;
                        Sg[row * 129 + col] = 1.0f / (1.0f + expf(-gv));
                    }
            }
    }
    __syncthreads();
    if (wm == 0) {
        #pragma unroll
        for (int mf = 0; mf < 4; ++mf)
            #pragma unroll
            for (int hi = 0; hi < 2; ++hi) {
                int row = mf * 16 + (lane >> 2) + 8 * hi;
                float bo = bout[rblk * 64 + row];
                float rs = 0.0f;
                #pragma unroll
                for (int nf = 0; nf < 4; ++nf)
                    #pragma unroll
                    for (int c01 = 0; c01 < 2; ++c01) {
                        int col = wn * 32 + nf * 8 + ((lane & 3) << 1) + c01;
                        rs += (acc[mf][nf][2 * hi + c01] + bo) * Sg[row * 129 + col];
                    }
                rs += __shfl_xor_sync(0xffffffffu, rs, 1);
                rs += __shfl_xor_sync(0xffffffffu, rs, 2);
                if ((lane & 3) == 0) red[row * 4 + wn] = rs;
            }
    }
    __syncthreads();
    if (tid < 64) {
        float s = red[tid * 4] + red[tid * 4 + 1] + red[tid * 4 + 2] + red[tid * 4 + 3];
        atomicAdd(&g_pooled[b * DMODEL + rblk * 64 + tid], s);
    }
}

// ---------------- kernel 5: mean scale + decoder ----------------------------
__global__ void k_final(const float* __restrict__ Wd,
                        const float* __restrict__ bd,
                        float* __restrict__ out) {
    int b = blockIdx.x;
    __shared__ float r[256];
    float s = 0.0f;
    for (int c = threadIdx.x; c < DMODEL; c += 256)
        s += Wd[c] * g_pooled[b * DMODEL + c];
    r[threadIdx.x] = s;
    __syncthreads();
    for (int st = 128; st > 0; st >>= 1) {
        if (threadIdx.x < st) r[threadIdx.x] += r[threadIdx.x + st];
        __syncthreads();
    }
    if (threadIdx.x == 0) out[b] = r[0] * (1.0f / (float)LEN) + bd[0];
}

// ---------------- launch -----------------------------------------------------
extern "C" void kernel_launch(void* const* d_in, const int* in_sizes, int n_in,
                              void* d_out, int out_size) {
    const float* u          = (const float*)d_in[0];
    const float* log_dt     = (const float*)d_in[1];
    const float* log_A_real = (const float*)d_in[2];
    const float* A_imag     = (const float*)d_in[3];
    const float* B_re       = (const float*)d_in[4];
    const float* B_im       = (const float*)d_in[5];
    const float* C_re       = (const float*)d_in[6];
    const float* C_im       = (const float*)d_in[7];
    const float* Dp         = (const float*)d_in[8];
    const float* W_out      = (const float*)d_in[9];
    const float* b_out      = (const float*)d_in[10];
    const float* W_dec      = (const float*)d_in[11];
    const float* b_dec      = (const float*)d_in[12];
    float* out = (float*)d_out;

    k_params<<<(DMODEL * DSTATE + 127) / 128, 128>>>(log_dt, log_A_real, A_imag,
                                                     B_re, B_im, C_re, C_im);
    k_packW<<<(8 * 32 * 2048) / 256, 256>>>(W_out);
    k_zero<<<(BATCH * DMODEL + 255) / 256, 256>>>();
    k_scan<<<(BATCH * DMODEL) / 4, 128>>>(u, Dp);
    dim3 gg(8, (BATCH * LEN) / 128);
    k_gemm<<<gg, 256>>>(b_out);
    k_final<<<BATCH, 256>>>(W_dec, b_dec, out);
}